// round 1
// baseline (speedup 1.0000x reference)
#include <cuda_runtime.h>
#include <cuda_bf16.h>

namespace {

constexpr int kS       = 2048;
constexpr int kD       = 64;
constexpr int kBH      = 32;     // B*H = 2*16
constexpr int kT       = 64;     // tile size for both q and k
constexpr int kThreads = 256;
constexpr int kPad     = 68;     // smem row stride (floats), breaks bank conflicts, keeps 16B alignment
constexpr float kScale = 0.125f; // 1/sqrt(64)

// exp(x) via 2^t decomposition, FMA-pipe only (avoids MUFU.EX2 throughput wall).
// Valid for x <= 0 (our inputs are score - rowmax <= 0). abs err ~2e-6 relative.
__device__ __forceinline__ float fast_exp(float x) {
    float t = x * 1.4426950408889634f;     // x * log2(e)
    t = fmaxf(t, -126.0f);                 // clamp: masked -1e30 scores -> ~1.2e-38 ~ 0
    float z = t + 12582912.0f;             // 1.5*2^23: round-to-nearest-int trick
    float n = z - 12582912.0f;
    float f = t - n;                       // f in [-0.5, 0.5]
    int   e = __float_as_int(z) - 0x4B400000;  // = (int)round(t)
    float p =               1.3333558146e-3f;
    p = __fmaf_rn(p, f,     9.6181291076e-3f);
    p = __fmaf_rn(p, f,     5.5504108664e-2f);
    p = __fmaf_rn(p, f,     2.4022650696e-1f);
    p = __fmaf_rn(p, f,     6.9314718056e-1f);
    p = __fmaf_rn(p, f,     1.0f);
    return p * __int_as_float((e + 127) << 23);
}

__global__ __launch_bounds__(kThreads)
void attn_kernel(const float* __restrict__ Qg, const float* __restrict__ Kg,
                 const float* __restrict__ Vg, float* __restrict__ Og,
                 float* __restrict__ Wg)
{
    // Buffer A: Qt (pass 1), Pt (pass 2).  Buffer B: Kt (pass 1), V (pass 2).
    __shared__ float smA[kT * kPad];
    __shared__ float smB[kT * kPad];

    const int qt  = blockIdx.x;        // q tile index (0..31)
    const int bh  = blockIdx.y;        // fused batch*head
    const int tid = threadIdx.x;
    const int tx  = tid & 15;          // 16 x 16 thread grid, 4x4 register block each
    const int ty  = tid >> 4;
    const int nkt = qt + 1;            // causal: only k-tiles <= q-tile

    const float* Qtile = Qg + ((size_t)bh * kS + (size_t)qt * kT) * kD;
    float* wrow = Wg + ((size_t)bh * kS + (size_t)qt * kT) * (size_t)kS;

    // ---- load Q tile transposed: smA[d][r] (so inner-loop loads are along rows) ----
    for (int f = tid; f < kT * kD / 4; f += kThreads) {
        int r  = f >> 4;
        int d0 = (f & 15) << 2;
        float4 v = reinterpret_cast<const float4*>(Qtile)[f];
        smA[(d0 + 0) * kPad + r] = v.x;
        smA[(d0 + 1) * kPad + r] = v.y;
        smA[(d0 + 2) * kPad + r] = v.z;
        smA[(d0 + 3) * kPad + r] = v.w;
    }
    __syncthreads();

    float m[4], l[4];
#pragma unroll
    for (int i = 0; i < 4; i++) { m[i] = -1e30f; l[i] = 0.0f; }

    // ================= PASS 1: scores -> gmem scratch, online max/sum =================
    for (int kt = 0; kt < nkt; kt++) {
        const float* Ktile = Kg + ((size_t)bh * kS + (size_t)kt * kT) * kD;
        for (int f = tid; f < kT * kD / 4; f += kThreads) {
            int r  = f >> 4;
            int d0 = (f & 15) << 2;
            float4 v = reinterpret_cast<const float4*>(Ktile)[f];
            smB[(d0 + 0) * kPad + r] = v.x;
            smB[(d0 + 1) * kPad + r] = v.y;
            smB[(d0 + 2) * kPad + r] = v.z;
            smB[(d0 + 3) * kPad + r] = v.w;
        }
        __syncthreads();

        float acc[4][4];
#pragma unroll
        for (int i = 0; i < 4; i++)
#pragma unroll
            for (int j = 0; j < 4; j++) acc[i][j] = 0.0f;

#pragma unroll 8
        for (int d = 0; d < kD; d++) {
            float4 qv = *reinterpret_cast<const float4*>(&smA[d * kPad + 4 * ty]);
            float4 kv = *reinterpret_cast<const float4*>(&smB[d * kPad + 4 * tx]);
            float qr[4] = {qv.x, qv.y, qv.z, qv.w};
            float kr[4] = {kv.x, kv.y, kv.z, kv.w};
#pragma unroll
            for (int i = 0; i < 4; i++)
#pragma unroll
                for (int j = 0; j < 4; j++)
                    acc[i][j] = __fmaf_rn(qr[i], kr[j], acc[i][j]);
        }

        const bool diag = (kt == qt);
#pragma unroll
        for (int i = 0; i < 4; i++)
#pragma unroll
            for (int j = 0; j < 4; j++) {
                float s = acc[i][j] * kScale;
                if (diag && (4 * tx + j > 4 * ty + i)) s = -1e30f;  // causal mask
                acc[i][j] = s;
            }

        // store raw (scaled, masked) scores to gmem scratch (stays in L2; same thread rereads)
#pragma unroll
        for (int i = 0; i < 4; i++) {
            *reinterpret_cast<float4*>(
                &wrow[(size_t)(4 * ty + i) * kS + (size_t)kt * kT + 4 * tx]) =
                make_float4(acc[i][0], acc[i][1], acc[i][2], acc[i][3]);
        }

        // online rowmax / rowsum across the 16 tx lanes sharing each row
#pragma unroll
        for (int i = 0; i < 4; i++) {
            float rm = fmaxf(fmaxf(acc[i][0], acc[i][1]), fmaxf(acc[i][2], acc[i][3]));
#pragma unroll
            for (int w = 1; w < 16; w <<= 1)
                rm = fmaxf(rm, __shfl_xor_sync(0xffffffffu, rm, w));
            float mn = fmaxf(m[i], rm);
            float es = fast_exp(acc[i][0] - mn) + fast_exp(acc[i][1] - mn)
                     + fast_exp(acc[i][2] - mn) + fast_exp(acc[i][3] - mn);
#pragma unroll
            for (int w = 1; w < 16; w <<= 1)
                es += __shfl_xor_sync(0xffffffffu, es, w);
            l[i] = l[i] * fast_exp(m[i] - mn) + es;
            m[i] = mn;
        }
        __syncthreads();
    }

    float rl[4];
#pragma unroll
    for (int i = 0; i < 4; i++) rl[i] = 1.0f / l[i];

    // ================= PASS 2: normalize -> weights out, P @ V -> output =================
    float o[4][4];
#pragma unroll
    for (int i = 0; i < 4; i++)
#pragma unroll
        for (int j = 0; j < 4; j++) o[i][j] = 0.0f;

    for (int kt = 0; kt < nkt; kt++) {
        const float* Vtile = Vg + ((size_t)bh * kS + (size_t)kt * kT) * kD;
        for (int f = tid; f < kT * kD / 4; f += kThreads) {
            int r  = f >> 4;
            int c4 = (f & 15) << 2;
            float4 v = reinterpret_cast<const float4*>(Vtile)[f];
            *reinterpret_cast<float4*>(&smB[r * kPad + c4]) = v;   // V row-major
        }

        const bool diag = (kt == qt);
#pragma unroll
        for (int i = 0; i < 4; i++) {
            size_t off = (size_t)(4 * ty + i) * kS + (size_t)kt * kT + 4 * tx;
            float4 sv = *reinterpret_cast<const float4*>(&wrow[off]);
            float pv[4];
            pv[0] = fast_exp(sv.x - m[i]) * rl[i];
            pv[1] = fast_exp(sv.y - m[i]) * rl[i];
            pv[2] = fast_exp(sv.z - m[i]) * rl[i];
            pv[3] = fast_exp(sv.w - m[i]) * rl[i];
            if (diag) {
#pragma unroll
                for (int j = 0; j < 4; j++)
                    if (4 * tx + j > 4 * ty + i) pv[j] = 0.0f;  // exact zeros, match ref underflow
            }
            *reinterpret_cast<float4*>(&wrow[off]) =
                make_float4(pv[0], pv[1], pv[2], pv[3]);
            // scatter P transposed: smA[c][r]
#pragma unroll
            for (int j = 0; j < 4; j++)
                smA[(4 * tx + j) * kPad + 4 * ty + i] = pv[j];
        }
        __syncthreads();

#pragma unroll 8
        for (int c = 0; c < kT; c++) {
            float4 pf = *reinterpret_cast<const float4*>(&smA[c * kPad + 4 * ty]);
            float4 vf = *reinterpret_cast<const float4*>(&smB[c * kPad + 4 * tx]);
            float pr[4] = {pf.x, pf.y, pf.z, pf.w};
            float vr[4] = {vf.x, vf.y, vf.z, vf.w};
#pragma unroll
            for (int i = 0; i < 4; i++)
#pragma unroll
                for (int j = 0; j < 4; j++)
                    o[i][j] = __fmaf_rn(pr[i], vr[j], o[i][j]);
        }
        __syncthreads();
    }

    // ---- zero the strictly-masked column range [nkt*64, S) for all 64 rows ----
    const int zc0 = nkt * kT;
    if (zc0 < kS) {
        const int r  = tid >> 2;          // 0..63
        const int lf = tid & 3;
        float4 z = make_float4(0.f, 0.f, 0.f, 0.f);
        float4* rowp = reinterpret_cast<float4*>(wrow + (size_t)r * kS);
        for (int c4 = (zc0 >> 2) + lf; c4 < (kS >> 2); c4 += 4)
            rowp[c4] = z;
    }

    // ---- write O tile ----
    float* Otile = Og + ((size_t)bh * kS + (size_t)qt * kT) * kD;
#pragma unroll
    for (int i = 0; i < 4; i++) {
        *reinterpret_cast<float4*>(&Otile[(4 * ty + i) * kD + 4 * tx]) =
            make_float4(o[i][0], o[i][1], o[i][2], o[i][3]);
    }
}

} // namespace

extern "C" void kernel_launch(void* const* d_in, const int* in_sizes, int n_in,
                              void* d_out, int out_size) {
    const float* Q = (const float*)d_in[0];
    const float* K = (const float*)d_in[1];
    const float* V = (const float*)d_in[2];
    // d_in[3] is the causal mask; it is tril by construction, we apply it analytically.
    (void)in_sizes; (void)n_in; (void)out_size;

    float* out = (float*)d_out;                       // [B,H,S,D] output
    float* w   = out + (size_t)kBH * kS * kD;         // [B,H,S,S] attn_weights

    dim3 grid(kS / kT, kBH);                          // (32 q-tiles, 32 bh)
    attn_kernel<<<grid, kThreads>>>(Q, K, V, out, w);
}

// round 3
// speedup vs baseline: 1.8609x; 1.8609x over previous
#include <cuda_runtime.h>
#include <cuda_bf16.h>
#include <cstdint>

namespace {

constexpr int kS  = 2048;
constexpr int kD  = 64;
constexpr int kBH = 32;
constexpr int kNE = kBH * kS * kD;        // 4,194,304 elements per tensor

// split-bf16 scratch planes (static __device__ = allowed scratch)
__device__ __align__(16) __nv_bfloat16 g_qh[kNE];
__device__ __align__(16) __nv_bfloat16 g_ql[kNE];
__device__ __align__(16) __nv_bfloat16 g_kh[kNE];
__device__ __align__(16) __nv_bfloat16 g_kl[kNE];
__device__ __align__(16) __nv_bfloat16 g_vh[kNE];
__device__ __align__(16) __nv_bfloat16 g_vl[kNE];

// smem layout: 6 tiles of [128 rows x 128B] = 16KB each -> 96KB total
constexpr int SM_QH = 0;
constexpr int SM_QL = 16384;
constexpr int SM_KH = 32768;
constexpr int SM_KL = 49152;
constexpr int SM_VH = 65536;
constexpr int SM_VL = 81920;
constexpr int SM_TOTAL = 98304;

__device__ __forceinline__ uint32_t cvta_sm(const void* p) {
    uint32_t a;
    asm("{ .reg .u64 t; cvta.to.shared.u64 t, %1; cvt.u32.u64 %0, t; }" : "=r"(a) : "l"(p));
    return a;
}

__device__ __forceinline__ void ldsm4(uint32_t* r, uint32_t a) {
    asm volatile("ldmatrix.sync.aligned.m8n8.x4.shared.b16 {%0,%1,%2,%3}, [%4];"
                 : "=r"(r[0]), "=r"(r[1]), "=r"(r[2]), "=r"(r[3]) : "r"(a));
}
__device__ __forceinline__ void ldsm4t(uint32_t* r, uint32_t a) {
    asm volatile("ldmatrix.sync.aligned.m8n8.x4.trans.shared.b16 {%0,%1,%2,%3}, [%4];"
                 : "=r"(r[0]), "=r"(r[1]), "=r"(r[2]), "=r"(r[3]) : "r"(a));
}

__device__ __forceinline__ void mma16816(float* d, const uint32_t* a, uint32_t b0, uint32_t b1) {
    asm volatile(
        "mma.sync.aligned.m16n8k16.row.col.f32.bf16.bf16.f32 "
        "{%0,%1,%2,%3}, {%4,%5,%6,%7}, {%8,%9}, {%0,%1,%2,%3};"
        : "+f"(d[0]), "+f"(d[1]), "+f"(d[2]), "+f"(d[3])
        : "r"(a[0]), "r"(a[1]), "r"(a[2]), "r"(a[3]), "r"(b0), "r"(b1));
}

// per-lane address for an ldmatrix.x4 over a 16x16 bf16 region at (row0, 16B-col c16)
// tiles are [row][128B] with 16B-chunk XOR swizzle: chunk' = chunk ^ (row & 7)
__device__ __forceinline__ uint32_t frag_addr(uint32_t tile, int row0, int c16, int lane) {
    int r = row0 + (lane & 15);
    int c = c16 + (lane >> 4);
    return tile + r * 128 + ((c ^ (r & 7)) << 4);
}

__device__ __forceinline__ void split2(float a, float b, uint32_t& hi, uint32_t& lo) {
    __nv_bfloat162 h = __floats2bfloat162_rn(a, b);
    __nv_bfloat162 l = __floats2bfloat162_rn(a - __bfloat162float(h.x),
                                             b - __bfloat162float(h.y));
    hi = *reinterpret_cast<uint32_t*>(&h);
    lo = *reinterpret_cast<uint32_t*>(&l);
}

// copy one [128 x 128B] tile (1024 uint4) into swizzled smem
__device__ __forceinline__ void fill_tile(char* smb, int off, const uint4* __restrict__ src, int tid) {
#pragma unroll
    for (int i = tid; i < 1024; i += 256) {
        int r = i >> 3, c = i & 7;
        *reinterpret_cast<uint4*>(smb + off + r * 128 + ((c ^ (r & 7)) << 4)) = src[i];
    }
}

// S[32] (8 n8-frags) = Q(16 rows) x K^T over this kt tile, cols [cloc, cloc+64)
__device__ __forceinline__ void qk_chunk(float* S, uint32_t smQh, uint32_t smQl,
                                         uint32_t smKh, uint32_t smKl,
                                         int warp, int cloc, int lane) {
#pragma unroll
    for (int i = 0; i < 32; i++) S[i] = 0.f;
#pragma unroll
    for (int kk = 0; kk < 4; kk++) {
        uint32_t qh[4], ql[4];
        ldsm4(qh, frag_addr(smQh, warp * 16, 2 * kk, lane));
        ldsm4(ql, frag_addr(smQl, warp * 16, 2 * kk, lane));
#pragma unroll
        for (int g2 = 0; g2 < 4; g2++) {
            uint32_t kh[4], kl[4];
            ldsm4(kh, frag_addr(smKh, cloc + g2 * 16, 2 * kk, lane));
            ldsm4(kl, frag_addr(smKl, cloc + g2 * 16, 2 * kk, lane));
            float* s0 = S + g2 * 8;
            float* s1 = S + g2 * 8 + 4;
            mma16816(s0, qh, kh[0], kh[2]);
            mma16816(s0, qh, kl[0], kl[2]);
            mma16816(s0, ql, kh[0], kh[2]);
            mma16816(s1, qh, kh[1], kh[3]);
            mma16816(s1, qh, kl[1], kl[3]);
            mma16816(s1, ql, kh[1], kh[3]);
        }
    }
}

// O += P(=S, normalized probs) x V over tokens [cloc, cloc+64)
__device__ __forceinline__ void pv_chunk(float* O, const float* P,
                                         uint32_t smVh, uint32_t smVl,
                                         int cloc, int lane) {
#pragma unroll
    for (int kk = 0; kk < 4; kk++) {
        const float* p = P + kk * 8;
        uint32_t ah[4], al[4];
        split2(p[0], p[1], ah[0], al[0]);
        split2(p[2], p[3], ah[1], al[1]);
        split2(p[4], p[5], ah[2], al[2]);
        split2(p[6], p[7], ah[3], al[3]);
#pragma unroll
        for (int g2 = 0; g2 < 4; g2++) {
            uint32_t vh[4], vl[4];
            ldsm4t(vh, frag_addr(smVh, cloc + kk * 16, 2 * g2, lane));
            ldsm4t(vl, frag_addr(smVl, cloc + kk * 16, 2 * g2, lane));
            float* o0 = O + g2 * 8;
            float* o1 = O + g2 * 8 + 4;
            mma16816(o0, ah, vh[0], vh[1]);
            mma16816(o0, ah, vl[0], vl[1]);
            mma16816(o0, al, vh[0], vh[1]);
            mma16816(o1, ah, vh[2], vh[3]);
            mma16816(o1, ah, vl[2], vl[3]);
            mma16816(o1, al, vh[2], vh[3]);
        }
    }
}

__global__ void split_kernel(const float4* __restrict__ Q, const float4* __restrict__ K,
                             const float4* __restrict__ V, int n4) {
    uint2* qh = reinterpret_cast<uint2*>(g_qh);
    uint2* ql = reinterpret_cast<uint2*>(g_ql);
    uint2* kh = reinterpret_cast<uint2*>(g_kh);
    uint2* kl = reinterpret_cast<uint2*>(g_kl);
    uint2* vh = reinterpret_cast<uint2*>(g_vh);
    uint2* vl = reinterpret_cast<uint2*>(g_vl);
    for (int i = blockIdx.x * blockDim.x + threadIdx.x; i < n4; i += gridDim.x * blockDim.x) {
        float4 q = Q[i];
        uint32_t h0, l0, h1, l1;
        split2(q.x * 0.125f, q.y * 0.125f, h0, l0);
        split2(q.z * 0.125f, q.w * 0.125f, h1, l1);
        qh[i] = make_uint2(h0, h1); ql[i] = make_uint2(l0, l1);
        float4 k = K[i];
        split2(k.x, k.y, h0, l0);
        split2(k.z, k.w, h1, l1);
        kh[i] = make_uint2(h0, h1); kl[i] = make_uint2(l0, l1);
        float4 v = V[i];
        split2(v.x, v.y, h0, l0);
        split2(v.z, v.w, h1, l1);
        vh[i] = make_uint2(h0, h1); vl[i] = make_uint2(l0, l1);
    }
}

__global__ void __launch_bounds__(256, 2)
attn_main(float* __restrict__ Og, float* __restrict__ Wg) {
    extern __shared__ char smb[];
    const uint32_t sb = cvta_sm(smb);
    const int tid  = threadIdx.x;
    const int warp = tid >> 5;
    const int lane = tid & 31;

    const int qt  = (gridDim.x - 1) - blockIdx.x;   // heavy tiles first
    const int bh  = blockIdx.y;
    const int nkt = qt + 1;

    float* wbase = Wg + ((size_t)bh * kS + (size_t)qt * 128) * kS;

    // zero strictly-masked columns [nkt*128, S) with evict-first stores
    {
        int c0 = nkt * 128;
        if (c0 < kS) {
            int per_row = (kS - c0) >> 2;
            int total   = 128 * per_row;
            float4 z = make_float4(0.f, 0.f, 0.f, 0.f);
            for (int i = tid; i < total; i += 256) {
                int r = i / per_row, c = i - r * per_row;
                __stcs(reinterpret_cast<float4*>(wbase + (size_t)r * kS + c0) + c, z);
            }
        }
    }

    // stage Q tile (hi/lo) once
    {
        size_t tb = ((size_t)bh * kS + (size_t)qt * 128) * kD / 8;   // uint4 index
        fill_tile(smb, SM_QH, reinterpret_cast<const uint4*>(g_qh) + tb, tid);
        fill_tile(smb, SM_QL, reinterpret_cast<const uint4*>(g_ql) + tb, tid);
    }
    __syncthreads();

    const int rowloc = warp * 16 + (lane >> 2);   // local q-row (lo); +8 for hi
    const int colb   = (lane & 3) * 2;

    // =================== PASS 1: row sums ===================
    float sum_lo = 0.f, sum_hi = 0.f;
    for (int kt = 0; kt < nkt; kt++) {
        size_t tb = ((size_t)bh * kS + (size_t)kt * 128) * kD / 8;
        fill_tile(smb, SM_KH, reinterpret_cast<const uint4*>(g_kh) + tb, tid);
        fill_tile(smb, SM_KL, reinterpret_cast<const uint4*>(g_kl) + tb, tid);
        __syncthreads();
        const bool diag = (kt == qt);
#pragma unroll
        for (int c = 0; c < 2; c++) {
            if (diag && c * 64 > warp * 16 + 15) continue;   // fully masked
            float S[32];
            qk_chunk(S, sb + SM_QH, sb + SM_QL, sb + SM_KH, sb + SM_KL, warp, c * 64, lane);
#pragma unroll
            for (int f = 0; f < 8; f++) {
                int c0 = c * 64 + f * 8 + colb;
                float e0 = __expf(S[4 * f + 0]);
                float e1 = __expf(S[4 * f + 1]);
                float e2 = __expf(S[4 * f + 2]);
                float e3 = __expf(S[4 * f + 3]);
                if (diag) {
                    if (c0     > rowloc)     e0 = 0.f;
                    if (c0 + 1 > rowloc)     e1 = 0.f;
                    if (c0     > rowloc + 8) e2 = 0.f;
                    if (c0 + 1 > rowloc + 8) e3 = 0.f;
                }
                sum_lo += e0 + e1;
                sum_hi += e2 + e3;
            }
        }
        __syncthreads();
    }
    sum_lo += __shfl_xor_sync(0xffffffffu, sum_lo, 1);
    sum_lo += __shfl_xor_sync(0xffffffffu, sum_lo, 2);
    sum_hi += __shfl_xor_sync(0xffffffffu, sum_hi, 1);
    sum_hi += __shfl_xor_sync(0xffffffffu, sum_hi, 2);
    const float rl_lo = 1.0f / sum_lo;
    const float rl_hi = 1.0f / sum_hi;

    // =================== PASS 2: weights + P@V ===================
    float O[32];
#pragma unroll
    for (int i = 0; i < 32; i++) O[i] = 0.f;

    for (int kt = 0; kt < nkt; kt++) {
        size_t tb = ((size_t)bh * kS + (size_t)kt * 128) * kD / 8;
        fill_tile(smb, SM_KH, reinterpret_cast<const uint4*>(g_kh) + tb, tid);
        fill_tile(smb, SM_KL, reinterpret_cast<const uint4*>(g_kl) + tb, tid);
        fill_tile(smb, SM_VH, reinterpret_cast<const uint4*>(g_vh) + tb, tid);
        fill_tile(smb, SM_VL, reinterpret_cast<const uint4*>(g_vl) + tb, tid);
        __syncthreads();
        const bool diag = (kt == qt);
        float* wlo = wbase + (size_t)rowloc * kS + kt * 128;
        float* whi = wlo + (size_t)8 * kS;
#pragma unroll
        for (int c = 0; c < 2; c++) {
            const bool skip = diag && (c * 64 > warp * 16 + 15);
            float S[32];
            if (!skip)
                qk_chunk(S, sb + SM_QH, sb + SM_QL, sb + SM_KH, sb + SM_KL, warp, c * 64, lane);
#pragma unroll
            for (int f = 0; f < 8; f++) {
                int c0 = c * 64 + f * 8 + colb;
                float e0, e1, e2, e3;
                if (skip) {
                    e0 = e1 = e2 = e3 = 0.f;
                } else {
                    e0 = __expf(S[4 * f + 0]) * rl_lo;
                    e1 = __expf(S[4 * f + 1]) * rl_lo;
                    e2 = __expf(S[4 * f + 2]) * rl_hi;
                    e3 = __expf(S[4 * f + 3]) * rl_hi;
                    if (diag) {
                        if (c0     > rowloc)     e0 = 0.f;
                        if (c0 + 1 > rowloc)     e1 = 0.f;
                        if (c0     > rowloc + 8) e2 = 0.f;
                        if (c0 + 1 > rowloc + 8) e3 = 0.f;
                    }
                }
                __stcs(reinterpret_cast<float2*>(wlo + c0), make_float2(e0, e1));
                __stcs(reinterpret_cast<float2*>(whi + c0), make_float2(e2, e3));
                S[4 * f + 0] = e0; S[4 * f + 1] = e1;
                S[4 * f + 2] = e2; S[4 * f + 3] = e3;
            }
            if (!skip)
                pv_chunk(O, S, sb + SM_VH, sb + SM_VL, c * 64, lane);
        }
        __syncthreads();
    }

    // write O
    {
        float* olo = Og + ((size_t)bh * kS + (size_t)qt * 128 + rowloc) * kD;
        float* ohi = olo + (size_t)8 * kD;
#pragma unroll
        for (int f = 0; f < 8; f++) {
            int d0 = f * 8 + colb;
            *reinterpret_cast<float2*>(olo + d0) = make_float2(O[4 * f + 0], O[4 * f + 1]);
            *reinterpret_cast<float2*>(ohi + d0) = make_float2(O[4 * f + 2], O[4 * f + 3]);
        }
    }
}

} // namespace

extern "C" void kernel_launch(void* const* d_in, const int* in_sizes, int n_in,
                              void* d_out, int out_size) {
    const float* Q = (const float*)d_in[0];
    const float* K = (const float*)d_in[1];
    const float* V = (const float*)d_in[2];
    (void)in_sizes; (void)n_in; (void)out_size;   // d_in[3] = tril mask, applied analytically

    float* out = (float*)d_out;                   // [B,H,S,D]
    float* w   = out + (size_t)kBH * kS * kD;     // [B,H,S,S]

    static bool attr_set = false;
    if (!attr_set) {
        cudaFuncSetAttribute(attn_main, cudaFuncAttributeMaxDynamicSharedMemorySize, SM_TOTAL);
        attr_set = true;
    }

    split_kernel<<<2048, 256>>>((const float4*)Q, (const float4*)K, (const float4*)V, kNE / 4);
    dim3 grid(kS / 128, kBH);
    attn_main<<<grid, 256, SM_TOTAL>>>(out, w);
}

// round 4
// speedup vs baseline: 2.0360x; 1.0941x over previous
#include <cuda_runtime.h>
#include <cuda_bf16.h>
#include <cstdint>

namespace {

constexpr int kS  = 2048;
constexpr int kD  = 64;
constexpr int kBH = 32;
constexpr int kNE = kBH * kS * kD;        // 4,194,304 elements per tensor

// split-bf16 scratch planes (static __device__ = allowed scratch)
__device__ __align__(16) __nv_bfloat16 g_qh[kNE];
__device__ __align__(16) __nv_bfloat16 g_ql[kNE];
__device__ __align__(16) __nv_bfloat16 g_kh[kNE];
__device__ __align__(16) __nv_bfloat16 g_kl[kNE];
__device__ __align__(16) __nv_bfloat16 g_vh[kNE];
__device__ __align__(16) __nv_bfloat16 g_vl[kNE];

// smem: 6 x 16KB tile slots = 96KB. Pass 1 reuses KH/KL slots as a KH double buffer.
constexpr int SM_QH = 0;
constexpr int SM_QL = 16384;
constexpr int SM_KH = 32768;
constexpr int SM_KL = 49152;
constexpr int SM_VH = 65536;
constexpr int SM_VL = 81920;
constexpr int SM_TOTAL = 98304;

__device__ __forceinline__ uint32_t cvta_sm(const void* p) {
    uint32_t a;
    asm("{ .reg .u64 t; cvta.to.shared.u64 t, %1; cvt.u32.u64 %0, t; }" : "=r"(a) : "l"(p));
    return a;
}

#define CP_COMMIT() asm volatile("cp.async.commit_group;" ::: "memory")
#define CP_WAIT(N)  asm volatile("cp.async.wait_group %0;" :: "n"(N) : "memory")

__device__ __forceinline__ void cp16(uint32_t dst, const void* src) {
    asm volatile("cp.async.cg.shared.global [%0], [%1], 16;" :: "r"(dst), "l"(src) : "memory");
}

// async-copy one [128 x 128B] tile (1024 uint4) into XOR-swizzled smem
__device__ __forceinline__ void fill_async(uint32_t smdst, const uint4* __restrict__ src, int tid) {
#pragma unroll
    for (int i = tid; i < 1024; i += 256) {
        int r = i >> 3, c = i & 7;
        cp16(smdst + r * 128 + ((c ^ (r & 7)) << 4), src + i);
    }
}

__device__ __forceinline__ void ldsm4(uint32_t* r, uint32_t a) {
    asm volatile("ldmatrix.sync.aligned.m8n8.x4.shared.b16 {%0,%1,%2,%3}, [%4];"
                 : "=r"(r[0]), "=r"(r[1]), "=r"(r[2]), "=r"(r[3]) : "r"(a));
}
__device__ __forceinline__ void ldsm4t(uint32_t* r, uint32_t a) {
    asm volatile("ldmatrix.sync.aligned.m8n8.x4.trans.shared.b16 {%0,%1,%2,%3}, [%4];"
                 : "=r"(r[0]), "=r"(r[1]), "=r"(r[2]), "=r"(r[3]) : "r"(a));
}

__device__ __forceinline__ void mma16816(float* d, const uint32_t* a, uint32_t b0, uint32_t b1) {
    asm volatile(
        "mma.sync.aligned.m16n8k16.row.col.f32.bf16.bf16.f32 "
        "{%0,%1,%2,%3}, {%4,%5,%6,%7}, {%8,%9}, {%0,%1,%2,%3};"
        : "+f"(d[0]), "+f"(d[1]), "+f"(d[2]), "+f"(d[3])
        : "r"(a[0]), "r"(a[1]), "r"(a[2]), "r"(a[3]), "r"(b0), "r"(b1));
}

__device__ __forceinline__ uint32_t frag_addr(uint32_t tile, int row0, int c16, int lane) {
    int r = row0 + (lane & 15);
    int c = c16 + (lane >> 4);
    return tile + r * 128 + ((c ^ (r & 7)) << 4);
}

__device__ __forceinline__ void split2(float a, float b, uint32_t& hi, uint32_t& lo) {
    __nv_bfloat162 h = __floats2bfloat162_rn(a, b);
    __nv_bfloat162 l = __floats2bfloat162_rn(a - __bfloat162float(h.x),
                                             b - __bfloat162float(h.y));
    hi = *reinterpret_cast<uint32_t*>(&h);
    lo = *reinterpret_cast<uint32_t*>(&l);
}

// pass-1 QK: 2 products (qh+ql)*kh over cols [cloc, cloc+64)
__device__ __forceinline__ void qk2_chunk(float* S, uint32_t smQh, uint32_t smQl,
                                          uint32_t smKh, int warp, int cloc, int lane) {
#pragma unroll
    for (int i = 0; i < 32; i++) S[i] = 0.f;
#pragma unroll
    for (int kk = 0; kk < 4; kk++) {
        uint32_t qh[4], ql[4];
        ldsm4(qh, frag_addr(smQh, warp * 16, 2 * kk, lane));
        ldsm4(ql, frag_addr(smQl, warp * 16, 2 * kk, lane));
#pragma unroll
        for (int g2 = 0; g2 < 4; g2++) {
            uint32_t kh[4];
            ldsm4(kh, frag_addr(smKh, cloc + g2 * 16, 2 * kk, lane));
            float* s0 = S + g2 * 8;
            float* s1 = S + g2 * 8 + 4;
            mma16816(s0, qh, kh[0], kh[2]);
            mma16816(s0, ql, kh[0], kh[2]);
            mma16816(s1, qh, kh[1], kh[3]);
            mma16816(s1, ql, kh[1], kh[3]);
        }
    }
}

// pass-2 QK: full 3-product split
__device__ __forceinline__ void qk3_chunk(float* S, uint32_t smQh, uint32_t smQl,
                                          uint32_t smKh, uint32_t smKl,
                                          int warp, int cloc, int lane) {
#pragma unroll
    for (int i = 0; i < 32; i++) S[i] = 0.f;
#pragma unroll
    for (int kk = 0; kk < 4; kk++) {
        uint32_t qh[4], ql[4];
        ldsm4(qh, frag_addr(smQh, warp * 16, 2 * kk, lane));
        ldsm4(ql, frag_addr(smQl, warp * 16, 2 * kk, lane));
#pragma unroll
        for (int g2 = 0; g2 < 4; g2++) {
            uint32_t kh[4], kl[4];
            ldsm4(kh, frag_addr(smKh, cloc + g2 * 16, 2 * kk, lane));
            ldsm4(kl, frag_addr(smKl, cloc + g2 * 16, 2 * kk, lane));
            float* s0 = S + g2 * 8;
            float* s1 = S + g2 * 8 + 4;
            mma16816(s0, qh, kh[0], kh[2]);
            mma16816(s0, qh, kl[0], kl[2]);
            mma16816(s0, ql, kh[0], kh[2]);
            mma16816(s1, qh, kh[1], kh[3]);
            mma16816(s1, qh, kl[1], kl[3]);
            mma16816(s1, ql, kh[1], kh[3]);
        }
    }
}

__device__ __forceinline__ void pv_chunk(float* O, const float* P,
                                         uint32_t smVh, uint32_t smVl,
                                         int cloc, int lane) {
#pragma unroll
    for (int kk = 0; kk < 4; kk++) {
        const float* p = P + kk * 8;
        uint32_t ah[4], al[4];
        split2(p[0], p[1], ah[0], al[0]);
        split2(p[2], p[3], ah[1], al[1]);
        split2(p[4], p[5], ah[2], al[2]);
        split2(p[6], p[7], ah[3], al[3]);
#pragma unroll
        for (int g2 = 0; g2 < 4; g2++) {
            uint32_t vh[4], vl[4];
            ldsm4t(vh, frag_addr(smVh, cloc + kk * 16, 2 * g2, lane));
            ldsm4t(vl, frag_addr(smVl, cloc + kk * 16, 2 * g2, lane));
            float* o0 = O + g2 * 8;
            float* o1 = O + g2 * 8 + 4;
            mma16816(o0, ah, vh[0], vh[1]);
            mma16816(o0, ah, vl[0], vl[1]);
            mma16816(o0, al, vh[0], vh[1]);
            mma16816(o1, ah, vh[2], vh[3]);
            mma16816(o1, ah, vl[2], vl[3]);
            mma16816(o1, al, vh[2], vh[3]);
        }
    }
}

__global__ void split_kernel(const float4* __restrict__ Q, const float4* __restrict__ K,
                             const float4* __restrict__ V, int n4) {
    uint2* qh = reinterpret_cast<uint2*>(g_qh);
    uint2* ql = reinterpret_cast<uint2*>(g_ql);
    uint2* kh = reinterpret_cast<uint2*>(g_kh);
    uint2* kl = reinterpret_cast<uint2*>(g_kl);
    uint2* vh = reinterpret_cast<uint2*>(g_vh);
    uint2* vl = reinterpret_cast<uint2*>(g_vl);
    for (int i = blockIdx.x * blockDim.x + threadIdx.x; i < n4; i += gridDim.x * blockDim.x) {
        float4 q = Q[i];
        uint32_t h0, l0, h1, l1;
        split2(q.x * 0.125f, q.y * 0.125f, h0, l0);
        split2(q.z * 0.125f, q.w * 0.125f, h1, l1);
        qh[i] = make_uint2(h0, h1); ql[i] = make_uint2(l0, l1);
        float4 k = K[i];
        split2(k.x, k.y, h0, l0);
        split2(k.z, k.w, h1, l1);
        kh[i] = make_uint2(h0, h1); kl[i] = make_uint2(l0, l1);
        float4 v = V[i];
        split2(v.x, v.y, h0, l0);
        split2(v.z, v.w, h1, l1);
        vh[i] = make_uint2(h0, h1); vl[i] = make_uint2(l0, l1);
    }
}

__global__ void __launch_bounds__(256, 2)
attn_main(float* __restrict__ Og, float* __restrict__ Wg) {
    extern __shared__ char smb[];
    const uint32_t sb = cvta_sm(smb);
    const int tid  = threadIdx.x;
    const int warp = tid >> 5;
    const int lane = tid & 31;

    const int qt  = (gridDim.x - 1) - blockIdx.x;   // heavy tiles first
    const int bh  = blockIdx.y;
    const int nkt = qt + 1;

    float* wbase = Wg + ((size_t)bh * kS + (size_t)qt * 128) * kS;

    // zero strictly-masked columns [nkt*128, S) with evict-first stores
    {
        int c0 = nkt * 128;
        if (c0 < kS) {
            int per_row = (kS - c0) >> 2;
            int total   = 128 * per_row;
            float4 z = make_float4(0.f, 0.f, 0.f, 0.f);
            for (int i = tid; i < total; i += 256) {
                int r = i / per_row, c = i - r * per_row;
                __stcs(reinterpret_cast<float4*>(wbase + (size_t)r * kS + c0) + c, z);
            }
        }
    }

    const size_t qtb = ((size_t)bh * kS + (size_t)qt * 128) * kD / 8;   // uint4 index

    // stage Q tile (hi/lo) once + pass-1 K[0]
    fill_async(sb + SM_QH, reinterpret_cast<const uint4*>(g_qh) + qtb, tid);
    fill_async(sb + SM_QL, reinterpret_cast<const uint4*>(g_ql) + qtb, tid);
    {
        size_t tb = ((size_t)bh * kS) * kD / 8;
        fill_async(sb + SM_KH, reinterpret_cast<const uint4*>(g_kh) + tb, tid);
    }
    CP_COMMIT();

    const int rowloc = warp * 16 + (lane >> 2);   // local q-row (lo); +8 for hi
    const int colb   = (lane & 3) * 2;

    // =================== PASS 1: row sums (2-product QK, KH only, dbl-buffered) ==========
    float sum_lo = 0.f, sum_hi = 0.f;
    for (int kt = 0; kt < nkt; kt++) {
        CP_WAIT(0);
        __syncthreads();
        const uint32_t kbuf = sb + ((kt & 1) ? SM_KL : SM_KH);
        if (kt + 1 < nkt) {
            size_t tb = ((size_t)bh * kS + (size_t)(kt + 1) * 128) * kD / 8;
            fill_async(sb + (((kt + 1) & 1) ? SM_KL : SM_KH),
                       reinterpret_cast<const uint4*>(g_kh) + tb, tid);
            CP_COMMIT();
        }
        const bool diag = (kt == qt);
#pragma unroll
        for (int c = 0; c < 2; c++) {
            if (diag && c * 64 > warp * 16 + 15) continue;   // fully masked
            float S[32];
            qk2_chunk(S, sb + SM_QH, sb + SM_QL, kbuf, warp, c * 64, lane);
#pragma unroll
            for (int f = 0; f < 8; f++) {
                int c0 = c * 64 + f * 8 + colb;
                float e0 = __expf(S[4 * f + 0]);
                float e1 = __expf(S[4 * f + 1]);
                float e2 = __expf(S[4 * f + 2]);
                float e3 = __expf(S[4 * f + 3]);
                if (diag) {
                    if (c0     > rowloc)     e0 = 0.f;
                    if (c0 + 1 > rowloc)     e1 = 0.f;
                    if (c0     > rowloc + 8) e2 = 0.f;
                    if (c0 + 1 > rowloc + 8) e3 = 0.f;
                }
                sum_lo += e0 + e1;
                sum_hi += e2 + e3;
            }
        }
    }
    sum_lo += __shfl_xor_sync(0xffffffffu, sum_lo, 1);
    sum_lo += __shfl_xor_sync(0xffffffffu, sum_lo, 2);
    sum_hi += __shfl_xor_sync(0xffffffffu, sum_hi, 1);
    sum_hi += __shfl_xor_sync(0xffffffffu, sum_hi, 2);
    const float rl_lo = 1.0f / sum_lo;
    const float rl_hi = 1.0f / sum_hi;

    __syncthreads();   // pass-1 reads done before pass-2 refills K slots

    // prologue pass 2: K[0] then V[0] as separate groups
    {
        size_t tb = ((size_t)bh * kS) * kD / 8;
        fill_async(sb + SM_KH, reinterpret_cast<const uint4*>(g_kh) + tb, tid);
        fill_async(sb + SM_KL, reinterpret_cast<const uint4*>(g_kl) + tb, tid);
        CP_COMMIT();
        fill_async(sb + SM_VH, reinterpret_cast<const uint4*>(g_vh) + tb, tid);
        fill_async(sb + SM_VL, reinterpret_cast<const uint4*>(g_vl) + tb, tid);
        CP_COMMIT();
    }

    // =================== PASS 2: weights + P@V (staggered K/V pipelining) ===============
    float O[32];
#pragma unroll
    for (int i = 0; i < 32; i++) O[i] = 0.f;

    for (int kt = 0; kt < nkt; kt++) {
        CP_WAIT(1);         // K[kt] resident (V[kt] may still fly)
        __syncthreads();
        const bool diag = (kt == qt);
        const bool pre  = (kt + 1 < nkt);
        float* wlo = wbase + (size_t)rowloc * kS + kt * 128;
        float* whi = wlo + (size_t)8 * kS;

        // QK for both 64-col chunks first (K buffer freed before refill)
        float S0[32], S1[32];
        {
            const bool skip1 = diag && (64 > warp * 16 + 15);
            qk3_chunk(S0, sb + SM_QH, sb + SM_QL, sb + SM_KH, sb + SM_KL, warp, 0, lane);
            if (!skip1)
                qk3_chunk(S1, sb + SM_QH, sb + SM_QL, sb + SM_KH, sb + SM_KL, warp, 64, lane);
            else
#pragma unroll
                for (int i = 0; i < 32; i++) S1[i] = 0.f;
        }
        __syncthreads();    // all warps done reading K
        if (pre) {          // prefetch K[kt+1]; hides behind epilogue + PV
            size_t tb = ((size_t)bh * kS + (size_t)(kt + 1) * 128) * kD / 8;
            fill_async(sb + SM_KH, reinterpret_cast<const uint4*>(g_kh) + tb, tid);
            fill_async(sb + SM_KL, reinterpret_cast<const uint4*>(g_kl) + tb, tid);
            CP_COMMIT();
        }

        // epilogue: exp, normalize, mask, store W
#pragma unroll
        for (int c = 0; c < 2; c++) {
            float* S = c ? S1 : S0;
            const bool skip = diag && (c * 64 > warp * 16 + 15);
#pragma unroll
            for (int f = 0; f < 8; f++) {
                int c0 = c * 64 + f * 8 + colb;
                float e0, e1, e2, e3;
                if (skip) {
                    e0 = e1 = e2 = e3 = 0.f;
                } else {
                    e0 = __expf(S[4 * f + 0]) * rl_lo;
                    e1 = __expf(S[4 * f + 1]) * rl_lo;
                    e2 = __expf(S[4 * f + 2]) * rl_hi;
                    e3 = __expf(S[4 * f + 3]) * rl_hi;
                    if (diag) {
                        if (c0     > rowloc)     e0 = 0.f;
                        if (c0 + 1 > rowloc)     e1 = 0.f;
                        if (c0     > rowloc + 8) e2 = 0.f;
                        if (c0 + 1 > rowloc + 8) e3 = 0.f;
                    }
                }
                __stcs(reinterpret_cast<float2*>(wlo + c0), make_float2(e0, e1));
                __stcs(reinterpret_cast<float2*>(whi + c0), make_float2(e2, e3));
                S[4 * f + 0] = e0; S[4 * f + 1] = e1;
                S[4 * f + 2] = e2; S[4 * f + 3] = e3;
            }
        }

        // V[kt] must be resident; K[kt+1] may still fly
        if (pre) CP_WAIT(1); else CP_WAIT(0);
        __syncthreads();

        {
            const bool skip1 = diag && (64 > warp * 16 + 15);
            pv_chunk(O, S0, sb + SM_VH, sb + SM_VL, 0, lane);
            if (!skip1)
                pv_chunk(O, S1, sb + SM_VH, sb + SM_VL, 64, lane);
        }
        __syncthreads();    // all warps done reading V
        if (pre) {          // prefetch V[kt+1]; hides behind next iter's QK + epilogue
            size_t tb = ((size_t)bh * kS + (size_t)(kt + 1) * 128) * kD / 8;
            fill_async(sb + SM_VH, reinterpret_cast<const uint4*>(g_vh) + tb, tid);
            fill_async(sb + SM_VL, reinterpret_cast<const uint4*>(g_vl) + tb, tid);
            CP_COMMIT();
        }
    }

    // write O
    {
        float* olo = Og + ((size_t)bh * kS + (size_t)qt * 128 + rowloc) * kD;
        float* ohi = olo + (size_t)8 * kD;
#pragma unroll
        for (int f = 0; f < 8; f++) {
            int d0 = f * 8 + colb;
            *reinterpret_cast<float2*>(olo + d0) = make_float2(O[4 * f + 0], O[4 * f + 1]);
            *reinterpret_cast<float2*>(ohi + d0) = make_float2(O[4 * f + 2], O[4 * f + 3]);
        }
    }
}

} // namespace

extern "C" void kernel_launch(void* const* d_in, const int* in_sizes, int n_in,
                              void* d_out, int out_size) {
    const float* Q = (const float*)d_in[0];
    const float* K = (const float*)d_in[1];
    const float* V = (const float*)d_in[2];
    (void)in_sizes; (void)n_in; (void)out_size;   // d_in[3] = tril mask, applied analytically

    float* out = (float*)d_out;                   // [B,H,S,D]
    float* w   = out + (size_t)kBH * kS * kD;     // [B,H,S,S]

    static bool attr_set = false;
    if (!attr_set) {
        cudaFuncSetAttribute(attn_main, cudaFuncAttributeMaxDynamicSharedMemorySize, SM_TOTAL);
        attr_set = true;
    }

    split_kernel<<<2048, 256>>>((const float4*)Q, (const float4*)K, (const float4*)V, kNE / 4);
    dim3 grid(kS / 128, kBH);
    attn_main<<<grid, 256, SM_TOTAL>>>(out, w);
}